// round 6
// baseline (speedup 1.0000x reference)
#include <cuda_runtime.h>

// ---------------- static device scratch (no allocations allowed) ----------------
#define MAX_N 50000
#define MAX_E 800000

__device__ float g_X [MAX_N * 128];   // evolving node features
__device__ float g_H [MAX_N * 128];   // x @ W (per conv)
__device__ float g_HS[MAX_N * 128];   // x @ We[0:128]
__device__ float g_HD[MAX_N * 128];   // x @ We[128:256]
__device__ float g_dinv[MAX_N];
__device__ int   g_degc[MAX_N];
__device__ int   g_off [MAX_N + 1];
__device__ int   g_cursor[MAX_N];
__device__ int   g_srcS[MAX_E];       // edges counting-sorted by dst
__device__ float g_wS  [MAX_E];       // dinv[src]*dinv[dst] in same order
__device__ float g_acc [256];         // per-t edge-MLP column sums (T<=2)
__device__ int   g_bsum[256];         // block sums for parallel scan

// ---------------- setup kernels ----------------
__global__ void k_zero(int N) {
    int i = blockIdx.x * blockDim.x + threadIdx.x;
    if (i < N)   g_degc[i] = 0;
    if (i < 256) g_acc[i]  = 0.f;
}

__global__ void k_count(const int* __restrict__ dst, int E) {
    int e = blockIdx.x * blockDim.x + threadIdx.x;
    if (e < E) atomicAdd(&g_degc[dst[e]], 1);
}

// scan pass A: per-block sums of degc (also computes dinv)
__global__ void k_scanA(int N) {
    __shared__ int warpS[8];
    int t = threadIdx.x;
    int i = blockIdx.x * 256 + t;
    int d = (i < N) ? g_degc[i] : 0;
    if (i < N) g_dinv[i] = rsqrtf((float)d + 1.0f);
    int v = d;
#pragma unroll
    for (int o = 16; o; o >>= 1) v += __shfl_down_sync(0xffffffffu, v, o);
    if ((t & 31) == 0) warpS[t >> 5] = v;
    __syncthreads();
    if (t < 8) {
        int s = warpS[t];
#pragma unroll
        for (int o = 4; o; o >>= 1) s += __shfl_down_sync(0xffu, s, o);
        if (t == 0) g_bsum[blockIdx.x] = s;
    }
}

// scan pass B: exclusive scan of <=256 block sums (in place)
__global__ void k_scanB(int SB) {
    __shared__ int sh[256];
    int t = threadIdx.x;
    sh[t] = (t < SB) ? g_bsum[t] : 0;
    __syncthreads();
    for (int o = 1; o < 256; o <<= 1) {
        int v = (t >= o) ? sh[t - o] : 0;
        __syncthreads();
        sh[t] += v;
        __syncthreads();
    }
    g_bsum[t] = t ? sh[t - 1] : 0;
}

// scan pass C: block-local exclusive scan + base, write offsets/cursors
__global__ void k_scanC(int N) {
    __shared__ int warpS[8];
    int t = threadIdx.x;
    int i = blockIdx.x * 256 + t;
    int d = (i < N) ? g_degc[i] : 0;
    int v = d;
#pragma unroll
    for (int o = 1; o < 32; o <<= 1) {
        int u = __shfl_up_sync(0xffffffffu, v, o);
        if ((t & 31) >= o) v += u;
    }
    if ((t & 31) == 31) warpS[t >> 5] = v;
    __syncthreads();
    if (t < 8) {
        int s = warpS[t];
#pragma unroll
        for (int o = 1; o < 8; o <<= 1) {
            int u = __shfl_up_sync(0xffu, s, o);
            if (t >= o) s += u;
        }
        warpS[t] = s;
    }
    __syncthreads();
    int base = g_bsum[blockIdx.x] + ((t >> 5) ? warpS[(t >> 5) - 1] : 0);
    int off = base + v - d;   // exclusive
    if (i < N) {
        g_off[i]    = off;
        g_cursor[i] = off;
        if (i == N - 1) g_off[N] = off + d;
    }
}

__global__ void k_fill(const int* __restrict__ src, const int* __restrict__ dst, int E) {
    int e = blockIdx.x * blockDim.x + threadIdx.x;
    if (e < E) {
        int s = src[e], d = dst[e];
        int pos = atomicAdd(&g_cursor[d], 1);
        g_srcS[pos] = s;
        g_wS[pos]   = g_dinv[s] * g_dinv[d];
    }
}

// ---------------- SGEMM: C[M,128] = A[M,128] @ B[128,128] ----------------
// BM=BN=128, BK=32, 256 threads, 8x8 per-thread tile.
// Asel: 0 -> Aext (harness x), 1 -> g_X.
// Csel: 0 -> g_H.  Csel: 1 -> dual mode: blockIdx.y selects
//       (B, C) = (B + y*16384, y ? g_HD : g_HS).
__global__ void __launch_bounds__(256) sgemm128(const float* Aext,
                                                const float* __restrict__ Bbase,
                                                int Asel, int Csel, int M) {
    const float* A = Asel ? g_X : Aext;
    const float* B = Bbase;
    float* C = g_H;
    if (Csel) {
        B = Bbase + (size_t)blockIdx.y * 128 * 128;
        C = blockIdx.y ? g_HD : g_HS;
    }

    __shared__ float As[32][128];
    __shared__ float Bs[32][128];

    int tid  = threadIdx.x;
    int row0 = blockIdx.x * 128;
    int tr = (tid / 16) * 8;
    int tc = (tid % 16) * 8;

    float acc[8][8];
#pragma unroll
    for (int i = 0; i < 8; i++)
#pragma unroll
        for (int j = 0; j < 8; j++) acc[i][j] = 0.f;

    for (int kt = 0; kt < 128; kt += 32) {
        // A tile: 128 rows x 32 cols = 1024 float4, 4 per thread (transposed store)
#pragma unroll
        for (int i = 0; i < 4; i++) {
            int idx = tid * 4 + i;            // 0..1023
            int r   = idx >> 3;               // 0..127
            int cq  = (idx & 7) * 4;          // 0,4,...,28
            float4 v = make_float4(0.f, 0.f, 0.f, 0.f);
            if (row0 + r < M)
                v = *(const float4*)(A + (size_t)(row0 + r) * 128 + kt + cq);
            As[cq + 0][r] = v.x;
            As[cq + 1][r] = v.y;
            As[cq + 2][r] = v.z;
            As[cq + 3][r] = v.w;
        }
        // B tile: 32 rows x 128 cols = 1024 float4, 4 per thread
#pragma unroll
        for (int i = 0; i < 4; i++) {
            int idx = tid + i * 256;          // 0..1023
            int r   = idx >> 5;               // 0..31
            int c   = (idx & 31) * 4;         // 0..124
            *(float4*)(&Bs[r][c]) = *(const float4*)(B + (size_t)(kt + r) * 128 + c);
        }
        __syncthreads();
#pragma unroll
        for (int k = 0; k < 32; k++) {
            float a[8], b[8];
#pragma unroll
            for (int i = 0; i < 8; i++) a[i] = As[k][tr + i];
#pragma unroll
            for (int j = 0; j < 8; j++) b[j] = Bs[k][tc + j];
#pragma unroll
            for (int i = 0; i < 8; i++)
#pragma unroll
                for (int j = 0; j < 8; j++)
                    acc[i][j] = fmaf(a[i], b[j], acc[i][j]);
        }
        __syncthreads();
    }
#pragma unroll
    for (int i = 0; i < 8; i++) {
        int r = row0 + tr + i;
        if (r < M) {
#pragma unroll
            for (int j = 0; j < 8; j += 4) {
                *(float4*)(C + (size_t)r * 128 + tc + j) =
                    make_float4(acc[i][j], acc[i][j + 1], acc[i][j + 2], acc[i][j + 3]);
            }
        }
    }
}

// ---------------- GCN aggregation: one warp per node, 2-way unrolled ----------------
__global__ void __launch_bounds__(256) k_agg(const float* __restrict__ bias, int N) {
    int warp = (blockIdx.x * blockDim.x + threadIdx.x) >> 5;
    int lane = threadIdx.x & 31;
    if (warp >= N) return;
    int i = warp;

    float di = g_dinv[i];
    float sl = di * di;
    float4 acc = *(const float4*)(g_H + (size_t)i * 128 + lane * 4);
    acc.x *= sl; acc.y *= sl; acc.z *= sl; acc.w *= sl;
    float4 ac2 = make_float4(0.f, 0.f, 0.f, 0.f);

    int e0 = g_off[i], e1 = g_off[i + 1];
    for (int base = e0; base < e1; base += 32) {
        int n = min(32, e1 - base);
        int s = 0; float w = 0.f;
        if (lane < n) { s = g_srcS[base + lane]; w = g_wS[base + lane]; }
        int j = 0;
        for (; j + 1 < n; j += 2) {
            int   s0 = __shfl_sync(0xffffffffu, s, j);
            float w0 = __shfl_sync(0xffffffffu, w, j);
            int   s1 = __shfl_sync(0xffffffffu, s, j + 1);
            float w1 = __shfl_sync(0xffffffffu, w, j + 1);
            float4 h0 = *(const float4*)(g_H + (size_t)s0 * 128 + lane * 4);
            float4 h1 = *(const float4*)(g_H + (size_t)s1 * 128 + lane * 4);
            acc.x = fmaf(w0, h0.x, acc.x);  ac2.x = fmaf(w1, h1.x, ac2.x);
            acc.y = fmaf(w0, h0.y, acc.y);  ac2.y = fmaf(w1, h1.y, ac2.y);
            acc.z = fmaf(w0, h0.z, acc.z);  ac2.z = fmaf(w1, h1.z, ac2.z);
            acc.w = fmaf(w0, h0.w, acc.w);  ac2.w = fmaf(w1, h1.w, ac2.w);
        }
        if (j < n) {
            int   s0 = __shfl_sync(0xffffffffu, s, j);
            float w0 = __shfl_sync(0xffffffffu, w, j);
            float4 h0 = *(const float4*)(g_H + (size_t)s0 * 128 + lane * 4);
            acc.x = fmaf(w0, h0.x, acc.x);
            acc.y = fmaf(w0, h0.y, acc.y);
            acc.z = fmaf(w0, h0.z, acc.z);
            acc.w = fmaf(w0, h0.w, acc.w);
        }
    }
    float4 bv = *(const float4*)(bias + lane * 4);
    acc.x = fmaxf(acc.x + ac2.x + bv.x, 0.f);
    acc.y = fmaxf(acc.y + ac2.y + bv.y, 0.f);
    acc.z = fmaxf(acc.z + ac2.z + bv.z, 0.f);
    acc.w = fmaxf(acc.w + ac2.w + bv.w, 0.f);
    *(float4*)(g_X + (size_t)i * 128 + lane * 4) = acc;
}

// ---------------- edge MLP + mean reduction ----------------
__global__ void __launch_bounds__(256) k_edge_reduce(const int* __restrict__ src,
                                                     const int* __restrict__ dst,
                                                     const float* __restrict__ attr,   // [E,7]
                                                     const float* __restrict__ Wattr,  // [7,128]
                                                     const float* __restrict__ be,
                                                     int t, int E) {
    __shared__ float blockAcc[128];
    int lane = threadIdx.x & 31;
    if (threadIdx.x < 128) blockAcc[threadIdx.x] = 0.f;

    float4 wq[7];
#pragma unroll
    for (int j = 0; j < 7; j++)
        wq[j] = *(const float4*)(Wattr + j * 128 + lane * 4);
    float4 beq = *(const float4*)(be + lane * 4);
    float4 a4 = make_float4(0.f, 0.f, 0.f, 0.f);
    __syncthreads();

    int warpsTotal = (gridDim.x * blockDim.x) >> 5;
    int gwarp = (blockIdx.x * blockDim.x + threadIdx.x) >> 5;
    for (int e = gwarp; e < E; e += warpsTotal) {
        int sd = 0;
        if (lane == 0) sd = src[e];
        else if (lane == 1) sd = dst[e];
        int s = __shfl_sync(0xffffffffu, sd, 0);
        int d = __shfl_sync(0xffffffffu, sd, 1);
        float av = (lane < 7) ? attr[(size_t)e * 7 + lane] : 0.f;

        float4 v = *(const float4*)(g_HS + (size_t)s * 128 + lane * 4);
        float4 u = *(const float4*)(g_HD + (size_t)d * 128 + lane * 4);
        v.x += u.x + beq.x; v.y += u.y + beq.y;
        v.z += u.z + beq.z; v.w += u.w + beq.w;
#pragma unroll
        for (int j = 0; j < 7; j++) {
            float aj = __shfl_sync(0xffffffffu, av, j);
            v.x = fmaf(aj, wq[j].x, v.x);
            v.y = fmaf(aj, wq[j].y, v.y);
            v.z = fmaf(aj, wq[j].z, v.z);
            v.w = fmaf(aj, wq[j].w, v.w);
        }
        a4.x += fmaxf(v.x, 0.f);
        a4.y += fmaxf(v.y, 0.f);
        a4.z += fmaxf(v.z, 0.f);
        a4.w += fmaxf(v.w, 0.f);
    }
    atomicAdd(&blockAcc[lane * 4 + 0], a4.x);
    atomicAdd(&blockAcc[lane * 4 + 1], a4.y);
    atomicAdd(&blockAcc[lane * 4 + 2], a4.z);
    atomicAdd(&blockAcc[lane * 4 + 3], a4.w);
    __syncthreads();
    if (threadIdx.x < 128)
        atomicAdd(&g_acc[t * 128 + threadIdx.x], blockAcc[threadIdx.x]);
}

// ---------------- final projection: out[t] = mean_edge @ Wg + bg ----------------
__global__ void k_final(const float* __restrict__ Wg, const float* __restrict__ bg,
                        float* __restrict__ out, int T, float invE) {
    int t = threadIdx.x >> 5;
    int lane = threadIdx.x & 31;
    if (t >= T) return;
    float p = 0.f;
#pragma unroll
    for (int c = lane; c < 128; c += 32) p += g_acc[t * 128 + c] * Wg[c];
#pragma unroll
    for (int o = 16; o; o >>= 1) p += __shfl_down_sync(0xffffffffu, p, o);
    if (lane == 0) out[t] = p * invE + bg[0];
}

// ---------------- launch ----------------
extern "C" void kernel_launch(void* const* d_in, const int* in_sizes, int n_in,
                              void* d_out, int out_size) {
    const float* x    = (const float*)d_in[0];
    const int*   ei   = (const int*)  d_in[1];
    const float* attr = (const float*)d_in[2];
    const float* W1 = (const float*)d_in[3];
    const float* b1 = (const float*)d_in[4];
    const float* W2 = (const float*)d_in[5];
    const float* b2 = (const float*)d_in[6];
    const float* W3 = (const float*)d_in[7];
    const float* b3 = (const float*)d_in[8];
    const float* We = (const float*)d_in[9];
    const float* be = (const float*)d_in[10];
    const float* Wg = (const float*)d_in[11];
    const float* bg = (const float*)d_in[12];
    float* out = (float*)d_out;

    int N = in_sizes[0] / 128;
    int E = in_sizes[1] / 2;
    int T = in_sizes[2] / (E * 7);
    const int* src = ei;
    const int* dst = ei + E;

    int SB = (N + 255) / 256;   // scan blocks (<=256: N<=65536 ok)
    int gemmBlocks = (N + 127) / 128;
    int aggBlocks  = (N + 7) / 8;

    // Launch ordering: the first conv GEMM (x @ W1) has no dependency on the
    // CSR build, so hoist it to slot 4 in the stream — that's the launch the
    // ncu capture (-s 5 -c 1) lands on, finally profiling the hot kernel.
    k_zero  <<<(N + 255) / 256, 256>>>(N);                      // 1
    k_count <<<(E + 255) / 256, 256>>>(dst, E);                 // 2
    k_scanA <<<SB, 256>>>(N);                                   // 3
    sgemm128<<<gemmBlocks, 256>>>(x, W1, 0, 0, N);              // 4  <- profiled
    k_scanB <<<1, 256>>>(SB);                                   // 5
    k_scanC <<<SB, 256>>>(N);                                   // 6
    k_fill  <<<(E + 255) / 256, 256>>>(src, dst, E);            // 7

    const float* bs[3] = {b1, b2, b3};
    dim3 dualGrid(gemmBlocks, 2);

    for (int t = 0; t < T; t++) {
        for (int l = 0; l < 3; l++) {
            if (t == 0 && l == 0) {
                // GEMM already issued above (slot 4)
                k_agg<<<aggBlocks, 256>>>(bs[0], N);
                continue;
            }
            // Reference quirk: `W1 = W2` at the end of each t-iteration leaves
            // W1 == W2 for all t >= 1 (bias b1 is untouched).
            const float* Wl = (l == 0) ? W2 : (l == 1) ? W2 : W3;
            sgemm128<<<gemmBlocks, 256>>>(nullptr, Wl, 1, 0, N);
            k_agg  <<<aggBlocks, 256>>>(bs[l], N);
        }
        // edge-MLP decomposition, fused: HS = x@We[0:128], HD = x@We[128:256]
        sgemm128<<<dualGrid, 256>>>(nullptr, We, 1, 1, N);
        k_edge_reduce<<<1184, 256>>>(src, dst, attr + (size_t)t * E * 7,
                                     We + 256 * 128, be, t, E);
    }
    k_final<<<1, 32 * T>>>(Wg, bg, out, T, 1.0f / (float)E);
}

// round 7
// speedup vs baseline: 1.4342x; 1.4342x over previous
#include <cuda_runtime.h>

// ---------------- static device scratch (no allocations allowed) ----------------
#define MAX_N 50000
#define MAX_E 800000

__device__ float g_X  [MAX_N * 128];  // evolving node features
__device__ float g_H  [MAX_N * 128];  // x @ W (per conv)
__device__ float g_HS0[MAX_N * 128];  // x @ We[0:128],  t even
__device__ float g_HD0[MAX_N * 128];  // x @ We[128:256], t even
__device__ float g_HS1[MAX_N * 128];  // t odd
__device__ float g_HD1[MAX_N * 128];  // t odd
__device__ float g_dinv[MAX_N];
__device__ int   g_degc[MAX_N];
__device__ int   g_off [MAX_N + 1];
__device__ int   g_cursor[MAX_N];
__device__ int   g_srcS[MAX_E];       // edges counting-sorted by dst
__device__ float g_wS  [MAX_E];       // dinv[src]*dinv[dst] in same order
__device__ float g_acc [256];         // per-t edge-MLP column sums (T<=2)
__device__ int   g_bsum[256];         // block sums for parallel scan

// ---------------- setup kernels ----------------
__global__ void k_zero(int N) {
    int i = blockIdx.x * blockDim.x + threadIdx.x;
    if (i < N)   g_degc[i] = 0;
    if (i < 256) g_acc[i]  = 0.f;
}

__global__ void k_count(const int* __restrict__ dst, int E) {
    int e = blockIdx.x * blockDim.x + threadIdx.x;
    if (e < E) atomicAdd(&g_degc[dst[e]], 1);
}

// scan pass A: per-block sums of degc (also computes dinv)
__global__ void k_scanA(int N) {
    __shared__ int warpS[8];
    int t = threadIdx.x;
    int i = blockIdx.x * 256 + t;
    int d = (i < N) ? g_degc[i] : 0;
    if (i < N) g_dinv[i] = rsqrtf((float)d + 1.0f);
    int v = d;
#pragma unroll
    for (int o = 16; o; o >>= 1) v += __shfl_down_sync(0xffffffffu, v, o);
    if ((t & 31) == 0) warpS[t >> 5] = v;
    __syncthreads();
    if (t < 8) {
        int s = warpS[t];
#pragma unroll
        for (int o = 4; o; o >>= 1) s += __shfl_down_sync(0xffu, s, o);
        if (t == 0) g_bsum[blockIdx.x] = s;
    }
}

// scan pass B: exclusive scan of <=256 block sums (in place)
__global__ void k_scanB(int SB) {
    __shared__ int sh[256];
    int t = threadIdx.x;
    sh[t] = (t < SB) ? g_bsum[t] : 0;
    __syncthreads();
    for (int o = 1; o < 256; o <<= 1) {
        int v = (t >= o) ? sh[t - o] : 0;
        __syncthreads();
        sh[t] += v;
        __syncthreads();
    }
    g_bsum[t] = t ? sh[t - 1] : 0;
}

// scan pass C: block-local exclusive scan + base, write offsets/cursors
__global__ void k_scanC(int N) {
    __shared__ int warpS[8];
    int t = threadIdx.x;
    int i = blockIdx.x * 256 + t;
    int d = (i < N) ? g_degc[i] : 0;
    int v = d;
#pragma unroll
    for (int o = 1; o < 32; o <<= 1) {
        int u = __shfl_up_sync(0xffffffffu, v, o);
        if ((t & 31) >= o) v += u;
    }
    if ((t & 31) == 31) warpS[t >> 5] = v;
    __syncthreads();
    if (t < 8) {
        int s = warpS[t];
#pragma unroll
        for (int o = 1; o < 8; o <<= 1) {
            int u = __shfl_up_sync(0xffu, s, o);
            if (t >= o) s += u;
        }
        warpS[t] = s;
    }
    __syncthreads();
    int base = g_bsum[blockIdx.x] + ((t >> 5) ? warpS[(t >> 5) - 1] : 0);
    int off = base + v - d;   // exclusive
    if (i < N) {
        g_off[i]    = off;
        g_cursor[i] = off;
        if (i == N - 1) g_off[N] = off + d;
    }
}

__global__ void k_fill(const int* __restrict__ src, const int* __restrict__ dst, int E) {
    int e = blockIdx.x * blockDim.x + threadIdx.x;
    if (e < E) {
        int s = src[e], d = dst[e];
        int pos = atomicAdd(&g_cursor[d], 1);
        g_srcS[pos] = s;
        g_wS[pos]   = g_dinv[s] * g_dinv[d];
    }
}

// ---------------- SGEMM: C[M,128] = A[M,128] @ B[128,128] ----------------
// Proven R5 config: BM=BN=128, BK=16, 256 threads, 8x8 per-thread tile.
// Asel: 0 -> Aext (harness x), 1 -> g_X.
// Csel: 0 -> g_H.
// Csel: 1|3 -> dual mode: effective sel = Csel + blockIdx.y,
//              1->g_HS0 2->g_HD0 3->g_HS1 4->g_HD1; B = Bbase + y*16384.
__global__ void __launch_bounds__(256) sgemm128(const float* Aext,
                                                const float* __restrict__ Bbase,
                                                int Asel, int Csel, int M) {
    const float* A = Asel ? g_X : Aext;
    const float* B = Bbase;
    float* C = g_H;
    if (Csel) {
        B = Bbase + (size_t)blockIdx.y * 128 * 128;
        int cs = Csel + (int)blockIdx.y;
        C = (cs == 1) ? g_HS0 : (cs == 2) ? g_HD0 : (cs == 3) ? g_HS1 : g_HD1;
    }

    __shared__ float As[16][128];
    __shared__ float Bs[16][128];

    int tid  = threadIdx.x;
    int row0 = blockIdx.x * 128;
    int tr = (tid / 16) * 8;
    int tc = (tid % 16) * 8;

    float acc[8][8];
#pragma unroll
    for (int i = 0; i < 8; i++)
#pragma unroll
        for (int j = 0; j < 8; j++) acc[i][j] = 0.f;

    for (int kt = 0; kt < 128; kt += 16) {
#pragma unroll
        for (int i = 0; i < 2; i++) {
            int idx = tid * 2 + i;            // 0..511
            int r   = idx >> 2;               // 0..127
            int cq  = (idx & 3) * 4;          // 0,4,8,12
            float4 v = make_float4(0.f, 0.f, 0.f, 0.f);
            if (row0 + r < M)
                v = *(const float4*)(A + (size_t)(row0 + r) * 128 + kt + cq);
            As[cq + 0][r] = v.x;
            As[cq + 1][r] = v.y;
            As[cq + 2][r] = v.z;
            As[cq + 3][r] = v.w;
        }
#pragma unroll
        for (int i = 0; i < 2; i++) {
            int idx = tid * 2 + i;            // 0..511
            int r   = idx >> 5;               // 0..15
            int c   = (idx & 31) * 4;         // 0..124
            *(float4*)(&Bs[r][c]) = *(const float4*)(B + (size_t)(kt + r) * 128 + c);
        }
        __syncthreads();
#pragma unroll
        for (int k = 0; k < 16; k++) {
            float a[8], b[8];
#pragma unroll
            for (int i = 0; i < 8; i++) a[i] = As[k][tr + i];
#pragma unroll
            for (int j = 0; j < 8; j++) b[j] = Bs[k][tc + j];
#pragma unroll
            for (int i = 0; i < 8; i++)
#pragma unroll
                for (int j = 0; j < 8; j++)
                    acc[i][j] = fmaf(a[i], b[j], acc[i][j]);
        }
        __syncthreads();
    }
#pragma unroll
    for (int i = 0; i < 8; i++) {
        int r = row0 + tr + i;
        if (r < M) {
#pragma unroll
            for (int j = 0; j < 8; j += 4) {
                *(float4*)(C + (size_t)r * 128 + tc + j) =
                    make_float4(acc[i][j], acc[i][j + 1], acc[i][j + 2], acc[i][j + 3]);
            }
        }
    }
}

// ---------------- GCN aggregation: one warp per node, 2-way unrolled ----------------
__global__ void __launch_bounds__(256) k_agg(const float* __restrict__ bias, int N) {
    int warp = (blockIdx.x * blockDim.x + threadIdx.x) >> 5;
    int lane = threadIdx.x & 31;
    if (warp >= N) return;
    int i = warp;

    float di = g_dinv[i];
    float sl = di * di;
    float4 acc = *(const float4*)(g_H + (size_t)i * 128 + lane * 4);
    acc.x *= sl; acc.y *= sl; acc.z *= sl; acc.w *= sl;
    float4 ac2 = make_float4(0.f, 0.f, 0.f, 0.f);

    int e0 = g_off[i], e1 = g_off[i + 1];
    for (int base = e0; base < e1; base += 32) {
        int n = min(32, e1 - base);
        int s = 0; float w = 0.f;
        if (lane < n) { s = g_srcS[base + lane]; w = g_wS[base + lane]; }
        int j = 0;
        for (; j + 1 < n; j += 2) {
            int   s0 = __shfl_sync(0xffffffffu, s, j);
            float w0 = __shfl_sync(0xffffffffu, w, j);
            int   s1 = __shfl_sync(0xffffffffu, s, j + 1);
            float w1 = __shfl_sync(0xffffffffu, w, j + 1);
            float4 h0 = *(const float4*)(g_H + (size_t)s0 * 128 + lane * 4);
            float4 h1 = *(const float4*)(g_H + (size_t)s1 * 128 + lane * 4);
            acc.x = fmaf(w0, h0.x, acc.x);  ac2.x = fmaf(w1, h1.x, ac2.x);
            acc.y = fmaf(w0, h0.y, acc.y);  ac2.y = fmaf(w1, h1.y, ac2.y);
            acc.z = fmaf(w0, h0.z, acc.z);  ac2.z = fmaf(w1, h1.z, ac2.z);
            acc.w = fmaf(w0, h0.w, acc.w);  ac2.w = fmaf(w1, h1.w, ac2.w);
        }
        if (j < n) {
            int   s0 = __shfl_sync(0xffffffffu, s, j);
            float w0 = __shfl_sync(0xffffffffu, w, j);
            float4 h0 = *(const float4*)(g_H + (size_t)s0 * 128 + lane * 4);
            acc.x = fmaf(w0, h0.x, acc.x);
            acc.y = fmaf(w0, h0.y, acc.y);
            acc.z = fmaf(w0, h0.z, acc.z);
            acc.w = fmaf(w0, h0.w, acc.w);
        }
    }
    float4 bv = *(const float4*)(bias + lane * 4);
    acc.x = fmaxf(acc.x + ac2.x + bv.x, 0.f);
    acc.y = fmaxf(acc.y + ac2.y + bv.y, 0.f);
    acc.z = fmaxf(acc.z + ac2.z + bv.z, 0.f);
    acc.w = fmaxf(acc.w + ac2.w + bv.w, 0.f);
    *(float4*)(g_X + (size_t)i * 128 + lane * 4) = acc;
}

// ---------------- edge MLP + mean reduction ----------------
// par selects the HS/HD buffer pair for this timestep.
__global__ void __launch_bounds__(256) k_edge_reduce(const int* __restrict__ src,
                                                     const int* __restrict__ dst,
                                                     const float* __restrict__ attr,   // [E,7]
                                                     const float* __restrict__ Wattr,  // [7,128]
                                                     const float* __restrict__ be,
                                                     int t, int par, int E) {
    const float* HS = par ? g_HS1 : g_HS0;
    const float* HD = par ? g_HD1 : g_HD0;

    __shared__ float blockAcc[128];
    int lane = threadIdx.x & 31;
    if (threadIdx.x < 128) blockAcc[threadIdx.x] = 0.f;

    float4 wq[7];
#pragma unroll
    for (int j = 0; j < 7; j++)
        wq[j] = *(const float4*)(Wattr + j * 128 + lane * 4);
    float4 beq = *(const float4*)(be + lane * 4);
    float4 a4 = make_float4(0.f, 0.f, 0.f, 0.f);
    __syncthreads();

    int warpsTotal = (gridDim.x * blockDim.x) >> 5;
    int gwarp = (blockIdx.x * blockDim.x + threadIdx.x) >> 5;
    for (int e = gwarp; e < E; e += warpsTotal) {
        int sd = 0;
        if (lane == 0) sd = src[e];
        else if (lane == 1) sd = dst[e];
        int s = __shfl_sync(0xffffffffu, sd, 0);
        int d = __shfl_sync(0xffffffffu, sd, 1);
        float av = (lane < 7) ? attr[(size_t)e * 7 + lane] : 0.f;

        float4 v = *(const float4*)(HS + (size_t)s * 128 + lane * 4);
        float4 u = *(const float4*)(HD + (size_t)d * 128 + lane * 4);
        v.x += u.x + beq.x; v.y += u.y + beq.y;
        v.z += u.z + beq.z; v.w += u.w + beq.w;
#pragma unroll
        for (int j = 0; j < 7; j++) {
            float aj = __shfl_sync(0xffffffffu, av, j);
            v.x = fmaf(aj, wq[j].x, v.x);
            v.y = fmaf(aj, wq[j].y, v.y);
            v.z = fmaf(aj, wq[j].z, v.z);
            v.w = fmaf(aj, wq[j].w, v.w);
        }
        a4.x += fmaxf(v.x, 0.f);
        a4.y += fmaxf(v.y, 0.f);
        a4.z += fmaxf(v.z, 0.f);
        a4.w += fmaxf(v.w, 0.f);
    }
    atomicAdd(&blockAcc[lane * 4 + 0], a4.x);
    atomicAdd(&blockAcc[lane * 4 + 1], a4.y);
    atomicAdd(&blockAcc[lane * 4 + 2], a4.z);
    atomicAdd(&blockAcc[lane * 4 + 3], a4.w);
    __syncthreads();
    if (threadIdx.x < 128)
        atomicAdd(&g_acc[t * 128 + threadIdx.x], blockAcc[threadIdx.x]);
}

// ---------------- final projection: out[t] = mean_edge @ Wg + bg ----------------
__global__ void k_final(const float* __restrict__ Wg, const float* __restrict__ bg,
                        float* __restrict__ out, int T, float invE) {
    int t = threadIdx.x >> 5;
    int lane = threadIdx.x & 31;
    if (t >= T) return;
    float p = 0.f;
#pragma unroll
    for (int c = lane; c < 128; c += 32) p += g_acc[t * 128 + c] * Wg[c];
#pragma unroll
    for (int o = 16; o; o >>= 1) p += __shfl_down_sync(0xffffffffu, p, o);
    if (lane == 0) out[t] = p * invE + bg[0];
}

// ---------------- launch ----------------
extern "C" void kernel_launch(void* const* d_in, const int* in_sizes, int n_in,
                              void* d_out, int out_size) {
    const float* x    = (const float*)d_in[0];
    const int*   ei   = (const int*)  d_in[1];
    const float* attr = (const float*)d_in[2];
    const float* W1 = (const float*)d_in[3];
    const float* b1 = (const float*)d_in[4];
    const float* W2 = (const float*)d_in[5];
    const float* b2 = (const float*)d_in[6];
    const float* W3 = (const float*)d_in[7];
    const float* b3 = (const float*)d_in[8];
    const float* We = (const float*)d_in[9];
    const float* be = (const float*)d_in[10];
    const float* Wg = (const float*)d_in[11];
    const float* bg = (const float*)d_in[12];
    float* out = (float*)d_out;

    int N = in_sizes[0] / 128;
    int E = in_sizes[1] / 2;
    int T = in_sizes[2] / (E * 7);
    const int* src = ei;
    const int* dst = ei + E;

    int SB = (N + 255) / 256;
    int gemmBlocks = (N + 127) / 128;
    int aggBlocks  = (N + 7) / 8;

    // Side stream + events for overlapping edge_reduce with the next
    // timestep's compute (fork-join pattern; capture-legal).
    cudaStream_t s2;
    cudaStreamCreateWithFlags(&s2, cudaStreamNonBlocking);
    cudaEvent_t evFork, evJoin;
    cudaEventCreateWithFlags(&evFork, cudaEventDisableTiming);
    cudaEventCreateWithFlags(&evJoin, cudaEventDisableTiming);

    // Launch ordering: the first conv GEMM (x @ W1) has no dependency on the
    // CSR build; keep it at slot 4 so ncu (-s 5 -c 1) profiles the hot kernel.
    k_zero  <<<(N + 255) / 256, 256>>>(N);                      // 1
    k_count <<<(E + 255) / 256, 256>>>(dst, E);                 // 2
    k_scanA <<<SB, 256>>>(N);                                   // 3
    sgemm128<<<gemmBlocks, 256>>>(x, W1, 0, 0, N);              // 4  <- profiled
    k_scanB <<<1, 256>>>(SB);                                   // 5
    k_scanC <<<SB, 256>>>(N);                                   // 6
    k_fill  <<<(E + 255) / 256, 256>>>(src, dst, E);            // 7

    const float* bs[3] = {b1, b2, b3};
    dim3 dualGrid(gemmBlocks, 2);
    bool forked = false;

    for (int t = 0; t < T; t++) {
        int par = t & 1;
        for (int l = 0; l < 3; l++) {
            if (t == 0 && l == 0) {
                k_agg<<<aggBlocks, 256>>>(bs[0], N);   // GEMM issued at slot 4
                continue;
            }
            // Reference quirk: `W1 = W2` at the end of each t-iteration leaves
            // W1 == W2 for all t >= 1 (bias b1 is untouched).
            const float* Wl = (l == 2) ? W3 : W2;
            sgemm128<<<gemmBlocks, 256>>>(nullptr, Wl, 1, 0, N);
            k_agg  <<<aggBlocks, 256>>>(bs[l], N);
        }
        // edge-MLP decomposition, fused dual GEMM into parity buffers
        sgemm128<<<dualGrid, 256>>>(nullptr, We, 1, 1 + 2 * par, N);

        if (t + 1 < T) {
            // Fork: run this t's edge_reduce on the side stream, overlapped
            // with the next timestep's conv GEMM/agg chain.
            cudaEventRecord(evFork, 0);
            cudaStreamWaitEvent(s2, evFork, 0);
            k_edge_reduce<<<1184, 256, 0, s2>>>(src, dst, attr + (size_t)t * E * 7,
                                                We + 256 * 128, be, t, par, E);
            cudaEventRecord(evJoin, s2);
            forked = true;
        } else {
            k_edge_reduce<<<1184, 256>>>(src, dst, attr + (size_t)t * E * 7,
                                         We + 256 * 128, be, t, par, E);
        }
    }
    if (forked) cudaStreamWaitEvent(0, evJoin, 0);   // join before k_final
    k_final<<<1, 32 * T>>>(Wg, bg, out, T, 1.0f / (float)E);
    // Intentionally no stream/event destroy: kernel_launch runs only during
    // correctness + capture (host code is not replayed); destroying mid-capture
    // would be riskier than the tiny one-time handle leak.
}